// round 1
// baseline (speedup 1.0000x reference)
#include <cuda_runtime.h>
#include <math.h>

// Problem constants
#define BATCH 2048
#define NACT  256
#define ED    200
#define RD    200
#define HD    400
#define AD    400            // action dim = ED + RD
#define K1    (ED + HD + RD) // 800
#define HUGE_F 1e9f

// Scratch (device globals; no allocation allowed)
__device__ float g_X [BATCH * K1];   // [2048, 800]
__device__ float g_H1[BATCH * AD];   // [2048, 400]
__device__ float g_X2[BATCH * AD];   // [2048, 400]

// ---------------------------------------------------------------------------
// Kernel 1: build X = cat([E_emb[e], H, Q_emb[q]])  -> g_X [B, 800]
// ---------------------------------------------------------------------------
__global__ void build_x_kernel(const int* __restrict__ e,
                               const int* __restrict__ q,
                               const float* __restrict__ H,
                               const float* __restrict__ ent_emb,
                               const float* __restrict__ rel_emb) {
    int idx = blockIdx.x * blockDim.x + threadIdx.x;
    if (idx >= BATCH * K1) return;
    int b = idx / K1;
    int k = idx - b * K1;
    float v;
    if (k < ED) {
        v = ent_emb[(long)e[b] * ED + k];
    } else if (k < ED + HD) {
        v = H[b * HD + (k - ED)];
    } else {
        v = rel_emb[(long)q[b] * RD + (k - ED - HD)];
    }
    g_X[idx] = v;
}

// ---------------------------------------------------------------------------
// Kernel 2: tiled fp32 GEMM  C[M,N] = A[M,K] @ B[K,N] + bias  (optional ReLU)
// BM=BN=64, BK=16, 256 threads, 4x4 micro-tile per thread.
// M % 64 == 0 and K % 16 == 0 are guaranteed here; only N needs guards.
// ---------------------------------------------------------------------------
#define BM 64
#define BN 64
#define BK 16
#define TM 4
#define TN 4

__global__ __launch_bounds__(256) void sgemm_bias_kernel(
    const float* __restrict__ A, const float* __restrict__ Bm,
    const float* __restrict__ bias, float* __restrict__ C,
    int M, int N, int K, int doRelu) {

    __shared__ float As[BK][BM];
    __shared__ float Bs[BK][BN];

    int tid = threadIdx.x;
    int tx = tid % 16;        // col group
    int ty = tid / 16;        // row group
    int bm = blockIdx.y * BM;
    int n0 = blockIdx.x * BN;

    // A-tile load mapping: one float4 per thread along K
    int a_m  = tid >> 2;            // 0..63
    int a_k  = (tid & 3) * 4;       // 0,4,8,12
    // B-tile load mapping: one float4 per thread along N
    int b_k  = tid >> 4;            // 0..15
    int b_n  = (tid & 15) * 4;      // 0..60

    float acc[TM][TN];
#pragma unroll
    for (int i = 0; i < TM; i++)
#pragma unroll
        for (int j = 0; j < TN; j++) acc[i][j] = 0.0f;

    for (int k0 = 0; k0 < K; k0 += BK) {
        // load A tile (transposed into As[k][m])
        {
            const float4 v = *reinterpret_cast<const float4*>(
                &A[(long)(bm + a_m) * K + k0 + a_k]);
            As[a_k + 0][a_m] = v.x;
            As[a_k + 1][a_m] = v.y;
            As[a_k + 2][a_m] = v.z;
            As[a_k + 3][a_m] = v.w;
        }
        // load B tile
        {
            int gn = n0 + b_n;
            const float* src = &Bm[(long)(k0 + b_k) * N + gn];
            if (gn + 3 < N) {
                float4 v = *reinterpret_cast<const float4*>(src);
                Bs[b_k][b_n + 0] = v.x;
                Bs[b_k][b_n + 1] = v.y;
                Bs[b_k][b_n + 2] = v.z;
                Bs[b_k][b_n + 3] = v.w;
            } else {
#pragma unroll
                for (int j = 0; j < 4; j++)
                    Bs[b_k][b_n + j] = (gn + j < N) ? src[j] : 0.0f;
            }
        }
        __syncthreads();

#pragma unroll
        for (int k = 0; k < BK; k++) {
            float4 a4 = *reinterpret_cast<const float4*>(&As[k][ty * TM]);
            float4 b4 = *reinterpret_cast<const float4*>(&Bs[k][tx * TN]);
            float a[TM] = {a4.x, a4.y, a4.z, a4.w};
            float b[TN] = {b4.x, b4.y, b4.z, b4.w};
#pragma unroll
            for (int i = 0; i < TM; i++)
#pragma unroll
                for (int j = 0; j < TN; j++)
                    acc[i][j] = fmaf(a[i], b[j], acc[i][j]);
        }
        __syncthreads();
    }

    // epilogue
#pragma unroll
    for (int i = 0; i < TM; i++) {
        int row = bm + ty * TM + i;
#pragma unroll
        for (int j = 0; j < TN; j++) {
            int col = n0 + tx * TN + j;
            if (col < N) {
                float c = acc[i][j] + bias[col];
                if (doRelu) c = fmaxf(c, 0.0f);
                C[(long)row * N + col] = c;
            }
        }
    }
}

// ---------------------------------------------------------------------------
// Kernel 3: per-batch-row scores + softmax + entropy.
// One block per batch row (2048 blocks), 256 threads = 8 warps.
// Warp-per-action: gathered float4 row loads, dot with X2 row in smem.
// ---------------------------------------------------------------------------
__global__ __launch_bounds__(256) void scores_kernel(
    const int* __restrict__ r_space, const int* __restrict__ e_space,
    const int* __restrict__ action_mask,
    const float* __restrict__ rel_emb, const float* __restrict__ ent_emb,
    float* __restrict__ out_dist, float* __restrict__ out_ent,
    int write_ent) {

    __shared__ float4 x2s[AD / 4];   // 100 float4 = 400 floats
    __shared__ float  sc[NACT];
    __shared__ float  red[8];

    int b    = blockIdx.x;
    int tid  = threadIdx.x;
    int warp = tid >> 5;
    int lane = tid & 31;

    // load X2 row into smem (coalesced float4)
    if (tid < AD / 4)
        x2s[tid] = reinterpret_cast<const float4*>(&g_X2[(long)b * AD])[tid];
    __syncthreads();

    // warp-per-action gathered dot products
    for (int a = warp; a < NACT; a += 8) {
        int ri = r_space[(long)b * NACT + a];
        int ei = e_space[(long)b * NACT + a];
        const float4* rp = reinterpret_cast<const float4*>(&rel_emb[(long)ri * RD]);
        const float4* ep = reinterpret_cast<const float4*>(&ent_emb[(long)ei * ED]);

        float acc = 0.0f;
#pragma unroll 2
        for (int i = lane; i < RD / 4; i += 32) {
            float4 v = __ldg(rp + i);
            float4 x = x2s[i];
            acc = fmaf(v.x, x.x, acc);
            acc = fmaf(v.y, x.y, acc);
            acc = fmaf(v.z, x.z, acc);
            acc = fmaf(v.w, x.w, acc);
        }
#pragma unroll 2
        for (int i = lane; i < ED / 4; i += 32) {
            float4 v = __ldg(ep + i);
            float4 x = x2s[RD / 4 + i];
            acc = fmaf(v.x, x.x, acc);
            acc = fmaf(v.y, x.y, acc);
            acc = fmaf(v.z, x.z, acc);
            acc = fmaf(v.w, x.w, acc);
        }
#pragma unroll
        for (int o = 16; o > 0; o >>= 1)
            acc += __shfl_xor_sync(0xFFFFFFFFu, acc, o);

        if (lane == 0) {
            float m = (float)action_mask[(long)b * NACT + a];
            sc[a] = acc - (1.0f - m) * HUGE_F;
        }
    }
    __syncthreads();

    // --- softmax over 256 scores ---
    float s = sc[tid];

    float wmax = s;
#pragma unroll
    for (int o = 16; o > 0; o >>= 1)
        wmax = fmaxf(wmax, __shfl_xor_sync(0xFFFFFFFFu, wmax, o));
    if (lane == 0) red[warp] = wmax;
    __syncthreads();
    float bmax = red[0];
#pragma unroll
    for (int w = 1; w < 8; w++) bmax = fmaxf(bmax, red[w]);
    __syncthreads();

    float e = expf(s - bmax);

    float wsum = e;
#pragma unroll
    for (int o = 16; o > 0; o >>= 1)
        wsum += __shfl_xor_sync(0xFFFFFFFFu, wsum, o);
    if (lane == 0) red[warp] = wsum;
    __syncthreads();
    float bsum = 0.0f;
#pragma unroll
    for (int w = 0; w < 8; w++) bsum += red[w];
    __syncthreads();

    float p = e / bsum;

    // entropy contribution: p * log(clip(p, 1e-20, 1))
    float t = p * logf(fmaxf(p, 1e-20f));
    float wt = t;
#pragma unroll
    for (int o = 16; o > 0; o >>= 1)
        wt += __shfl_xor_sync(0xFFFFFFFFu, wt, o);
    if (lane == 0) red[warp] = wt;
    __syncthreads();

    out_dist[(long)b * NACT + tid] = p;

    if (tid == 0 && write_ent) {
        float ts = 0.0f;
#pragma unroll
        for (int w = 0; w < 8; w++) ts += red[w];
        out_ent[b] = -ts;
    }
}

// ---------------------------------------------------------------------------
// Launch
// ---------------------------------------------------------------------------
extern "C" void kernel_launch(void* const* d_in, const int* in_sizes, int n_in,
                              void* d_out, int out_size) {
    const int*   e           = (const int*)  d_in[0];
    const int*   q           = (const int*)  d_in[1];
    const int*   r_space     = (const int*)  d_in[2];
    const int*   e_space     = (const int*)  d_in[3];
    const int*   action_mask = (const int*)  d_in[4];
    const float* H           = (const float*)d_in[5];
    const float* entity_emb  = (const float*)d_in[6];
    const float* relation_emb= (const float*)d_in[7];
    const float* W1          = (const float*)d_in[8];
    const float* b1          = (const float*)d_in[9];
    const float* W2          = (const float*)d_in[10];
    const float* b2          = (const float*)d_in[11];

    float* out_dist = (float*)d_out;
    float* out_ent  = out_dist + (long)BATCH * NACT;
    int write_ent = (out_size >= BATCH * NACT + BATCH) ? 1 : 0;

    float* X  = nullptr; cudaGetSymbolAddress((void**)&X,  g_X);
    float* H1 = nullptr; cudaGetSymbolAddress((void**)&H1, g_H1);
    float* X2 = nullptr; cudaGetSymbolAddress((void**)&X2, g_X2);

    // 1) build X
    {
        int total = BATCH * K1;
        build_x_kernel<<<(total + 255) / 256, 256>>>(e, q, H, entity_emb, relation_emb);
    }
    // 2) H1 = relu(X @ W1 + b1)
    {
        dim3 grid((AD + BN - 1) / BN, BATCH / BM);
        sgemm_bias_kernel<<<grid, 256>>>(X, W1, b1, H1, BATCH, AD, K1, 1);
    }
    // 3) X2 = H1 @ W2 + b2
    {
        dim3 grid((AD + BN - 1) / BN, BATCH / BM);
        sgemm_bias_kernel<<<grid, 256>>>(H1, W2, b2, X2, BATCH, AD, AD, 0);
    }
    // 4) scores + softmax + entropy
    {
        scores_kernel<<<BATCH, 256>>>(r_space, e_space, action_mask,
                                      relation_emb, entity_emb,
                                      out_dist, out_ent, write_ent);
    }
}

// round 2
// speedup vs baseline: 1.2408x; 1.2408x over previous
#include <cuda_runtime.h>
#include <math.h>

// Problem constants
#define BATCH 2048
#define NACT  256
#define ED    200
#define RD    200
#define HD    400
#define AD    400            // action dim = ED + RD
#define K1    (ED + HD + RD) // 800
#define NRELPAD 512          // 500 relations padded to 512
#define HUGE_F 1e9f

// Scratch (device globals; no allocation allowed)
__device__ float g_H1  [BATCH * AD];       // [2048, 400]
__device__ float g_X2  [BATCH * AD];       // [2048, 400]
__device__ float g_Srel[BATCH * NRELPAD];  // [2048, 512] rel-part scores

__device__ __forceinline__ float dot4(float4 a, float4 b) {
    return fmaf(a.x, b.x, fmaf(a.y, b.y, fmaf(a.z, b.z, a.w * b.w)));
}

// ---------------------------------------------------------------------------
// Kernel 1/2: tiled fp32 GEMM  C[M,N] = A[M,K] @ B[K,N] + bias (opt ReLU).
// FUSED variant materializes A = cat([E_emb[e], H, Q_emb[q]]) on the fly.
// BM=BN=64, BK=16, 256 threads, 4x4 micro-tile.
// ---------------------------------------------------------------------------
#define BM 64
#define BN 64
#define BK 16
#define TM 4
#define TN 4

template <bool FUSED>
__global__ __launch_bounds__(256) void sgemm_bias_kernel(
    const float* __restrict__ A, const float* __restrict__ Bm,
    const float* __restrict__ bias, float* __restrict__ C,
    int M, int N, int K, int doRelu,
    const int* __restrict__ e, const int* __restrict__ q,
    const float* __restrict__ H,
    const float* __restrict__ ent_emb, const float* __restrict__ rel_emb) {

    __shared__ float As[BK][BM];
    __shared__ float Bs[BK][BN];

    int tid = threadIdx.x;
    int tx = tid % 16;
    int ty = tid / 16;
    int bm = blockIdx.y * BM;
    int n0 = blockIdx.x * BN;

    int a_m = tid >> 2;           // 0..63
    int a_k = (tid & 3) * 4;      // 0,4,8,12
    int b_k = tid >> 4;           // 0..15
    int b_n = (tid & 15) * 4;     // 0..60

    // For fused-X loads: cache gather indices for this thread's A row
    int arow = bm + a_m;
    int eR = 0, qR = 0;
    if (FUSED) { eR = e[arow]; qR = q[arow]; }

    float acc[TM][TN];
#pragma unroll
    for (int i = 0; i < TM; i++)
#pragma unroll
        for (int j = 0; j < TN; j++) acc[i][j] = 0.0f;

    for (int k0 = 0; k0 < K; k0 += BK) {
        // ---- load A tile (transposed into As[k][m]) ----
        {
            int k = k0 + a_k;
            float4 v;
            if (FUSED) {
                // X = cat([ent_emb[e] (200), H (400), rel_emb[q] (200)])
                // float4 chunks never straddle the 200/600 boundaries.
                const float* src;
                if (k < ED)            src = &ent_emb[(long)eR * ED + k];
                else if (k < ED + HD)  src = &H[(long)arow * HD + (k - ED)];
                else                   src = &rel_emb[(long)qR * RD + (k - ED - HD)];
                v = *reinterpret_cast<const float4*>(src);
            } else {
                v = *reinterpret_cast<const float4*>(&A[(long)arow * K + k]);
            }
            As[a_k + 0][a_m] = v.x;
            As[a_k + 1][a_m] = v.y;
            As[a_k + 2][a_m] = v.z;
            As[a_k + 3][a_m] = v.w;
        }
        // ---- load B tile ----
        {
            int gn = n0 + b_n;
            const float* src = &Bm[(long)(k0 + b_k) * N + gn];
            if (gn + 3 < N) {
                float4 v = *reinterpret_cast<const float4*>(src);
                Bs[b_k][b_n + 0] = v.x;
                Bs[b_k][b_n + 1] = v.y;
                Bs[b_k][b_n + 2] = v.z;
                Bs[b_k][b_n + 3] = v.w;
            } else {
#pragma unroll
                for (int j = 0; j < 4; j++)
                    Bs[b_k][b_n + j] = (gn + j < N) ? src[j] : 0.0f;
            }
        }
        __syncthreads();

#pragma unroll
        for (int k = 0; k < BK; k++) {
            float4 a4 = *reinterpret_cast<const float4*>(&As[k][ty * TM]);
            float4 b4 = *reinterpret_cast<const float4*>(&Bs[k][tx * TN]);
            float a[TM] = {a4.x, a4.y, a4.z, a4.w};
            float b[TN] = {b4.x, b4.y, b4.z, b4.w};
#pragma unroll
            for (int i = 0; i < TM; i++)
#pragma unroll
                for (int j = 0; j < TN; j++)
                    acc[i][j] = fmaf(a[i], b[j], acc[i][j]);
        }
        __syncthreads();
    }

#pragma unroll
    for (int i = 0; i < TM; i++) {
        int row = bm + ty * TM + i;
#pragma unroll
        for (int j = 0; j < TN; j++) {
            int col = n0 + tx * TN + j;
            if (col < N) {
                float c = acc[i][j] + bias[col];
                if (doRelu) c = fmaxf(c, 0.0f);
                C[(long)row * N + col] = c;
            }
        }
    }
}

// ---------------------------------------------------------------------------
// Kernel 3: S_rel[b, r] = rel_emb[r] . X2[b, 0:200]   (NT GEMM, K=200)
// BM=BN=64, BK=8, 256 threads, 4x4 micro-tile. Output padded to 512 cols.
// ---------------------------------------------------------------------------
__global__ __launch_bounds__(256) void srel_gemm_kernel(
    const float* __restrict__ X2, const float* __restrict__ rel_emb,
    float* __restrict__ Srel, int NR) {

    __shared__ float As[8][BM];
    __shared__ float Bs[8][BN];

    int tid = threadIdx.x;
    int tx = tid % 16;
    int ty = tid / 16;
    int bm = blockIdx.y * BM;
    int n0 = blockIdx.x * BN;

    int l_r = tid >> 2;           // 0..63 (row within tile)
    int l_k = (tid & 3) * 2;      // 0,2,4,6

    float acc[TM][TN];
#pragma unroll
    for (int i = 0; i < TM; i++)
#pragma unroll
        for (int j = 0; j < TN; j++) acc[i][j] = 0.0f;

    int brow = n0 + l_r;          // global relation row
    bool bvalid = brow < NR;

    for (int k0 = 0; k0 < RD; k0 += 8) {
        // A: X2[bm+l_r, k0+l_k .. +1]  (row stride AD=400; use first 200 cols)
        {
            float2 v = *reinterpret_cast<const float2*>(
                &X2[(long)(bm + l_r) * AD + k0 + l_k]);
            As[l_k + 0][l_r] = v.x;
            As[l_k + 1][l_r] = v.y;
        }
        // B (transposed): rel_emb[brow, k0+l_k .. +1]
        {
            float2 v = make_float2(0.0f, 0.0f);
            if (bvalid)
                v = *reinterpret_cast<const float2*>(
                    &rel_emb[(long)brow * RD + k0 + l_k]);
            Bs[l_k + 0][l_r] = v.x;
            Bs[l_k + 1][l_r] = v.y;
        }
        __syncthreads();

#pragma unroll
        for (int k = 0; k < 8; k++) {
            float4 a4 = *reinterpret_cast<const float4*>(&As[k][ty * TM]);
            float4 b4 = *reinterpret_cast<const float4*>(&Bs[k][tx * TN]);
            float a[TM] = {a4.x, a4.y, a4.z, a4.w};
            float b[TN] = {b4.x, b4.y, b4.z, b4.w};
#pragma unroll
            for (int i = 0; i < TM; i++)
#pragma unroll
                for (int j = 0; j < TN; j++)
                    acc[i][j] = fmaf(a[i], b[j], acc[i][j]);
        }
        __syncthreads();
    }

    // store (padded cols: no guard needed, padding never read)
#pragma unroll
    for (int i = 0; i < TM; i++) {
        int row = bm + ty * TM + i;
#pragma unroll
        for (int j = 0; j < TN; j++) {
            int col = n0 + tx * TN + j;
            Srel[(long)row * NRELPAD + col] = acc[i][j];
        }
    }
}

// ---------------------------------------------------------------------------
// Kernel 4: entity gather-dot + rel lookup + softmax + entropy.
// One block per batch row; warp-per-action (2 actions per iteration for MLP);
// X2 entity-half held in registers (lane-sliced), S_rel row in smem.
// ---------------------------------------------------------------------------
__global__ __launch_bounds__(256) void scores_kernel(
    const int* __restrict__ r_space, const int* __restrict__ e_space,
    const int* __restrict__ action_mask,
    const float* __restrict__ ent_emb,
    float* __restrict__ out_dist, float* __restrict__ out_ent,
    int write_ent) {

    __shared__ float srel_s[NRELPAD];
    __shared__ float sc[NACT];
    __shared__ float red[8];

    int b    = blockIdx.x;
    int tid  = threadIdx.x;
    int warp = tid >> 5;
    int lane = tid & 31;

    // load S_rel row (512 floats, coalesced)
    if (tid < NRELPAD / 4)
        reinterpret_cast<float4*>(srel_s)[tid] =
            reinterpret_cast<const float4*>(&g_Srel[(long)b * NRELPAD])[tid];

    // X2 entity half (cols 200..399 = float4 chunks 50..99) into registers:
    // lane holds chunk lane and (if lane<18) chunk lane+32.
    const float4* x2p = reinterpret_cast<const float4*>(&g_X2[(long)b * AD]);
    float4 x2a = x2p[50 + lane];
    bool hasB  = lane < (ED / 4 - 32);   // lane < 18
    float4 x2b = hasB ? x2p[50 + 32 + lane] : make_float4(0.f, 0.f, 0.f, 0.f);
    __syncthreads();

    const long base = (long)b * NACT;

    // 2 actions per warp iteration (a and a+8), 16 iterations total per warp
    for (int a = warp; a < NACT; a += 16) {
        int a2 = a + 8;
        int ei1 = e_space[base + a];
        int ei2 = e_space[base + a2];
        const float4* p1 = reinterpret_cast<const float4*>(&ent_emb[(long)ei1 * ED]);
        const float4* p2 = reinterpret_cast<const float4*>(&ent_emb[(long)ei2 * ED]);

        float4 v1a = __ldg(p1 + lane);
        float4 v2a = __ldg(p2 + lane);
        float4 v1b = make_float4(0.f, 0.f, 0.f, 0.f);
        float4 v2b = make_float4(0.f, 0.f, 0.f, 0.f);
        if (hasB) { v1b = __ldg(p1 + 32 + lane); v2b = __ldg(p2 + 32 + lane); }

        float acc1 = dot4(v1a, x2a) + dot4(v1b, x2b);
        float acc2 = dot4(v2a, x2a) + dot4(v2b, x2b);

#pragma unroll
        for (int o = 16; o > 0; o >>= 1) {
            acc1 += __shfl_xor_sync(0xFFFFFFFFu, acc1, o);
            acc2 += __shfl_xor_sync(0xFFFFFFFFu, acc2, o);
        }

        if (lane == 0) {
            int ri1 = r_space[base + a];
            int ri2 = r_space[base + a2];
            float m1 = (float)action_mask[base + a];
            float m2 = (float)action_mask[base + a2];
            sc[a]  = acc1 + srel_s[ri1] - (1.0f - m1) * HUGE_F;
            sc[a2] = acc2 + srel_s[ri2] - (1.0f - m2) * HUGE_F;
        }
    }
    __syncthreads();

    // --- softmax over 256 scores ---
    float s = sc[tid];

    float wmax = s;
#pragma unroll
    for (int o = 16; o > 0; o >>= 1)
        wmax = fmaxf(wmax, __shfl_xor_sync(0xFFFFFFFFu, wmax, o));
    if (lane == 0) red[warp] = wmax;
    __syncthreads();
    float bmax = red[0];
#pragma unroll
    for (int w = 1; w < 8; w++) bmax = fmaxf(bmax, red[w]);
    __syncthreads();

    float e = expf(s - bmax);

    float wsum = e;
#pragma unroll
    for (int o = 16; o > 0; o >>= 1)
        wsum += __shfl_xor_sync(0xFFFFFFFFu, wsum, o);
    if (lane == 0) red[warp] = wsum;
    __syncthreads();
    float bsum = 0.0f;
#pragma unroll
    for (int w = 0; w < 8; w++) bsum += red[w];
    __syncthreads();

    float p = e / bsum;

    float t = p * logf(fmaxf(p, 1e-20f));
    float wt = t;
#pragma unroll
    for (int o = 16; o > 0; o >>= 1)
        wt += __shfl_xor_sync(0xFFFFFFFFu, wt, o);
    if (lane == 0) red[warp] = wt;
    __syncthreads();

    out_dist[base + tid] = p;

    if (tid == 0 && write_ent) {
        float ts = 0.0f;
#pragma unroll
        for (int w = 0; w < 8; w++) ts += red[w];
        out_ent[b] = -ts;
    }
}

// ---------------------------------------------------------------------------
// Launch
// ---------------------------------------------------------------------------
extern "C" void kernel_launch(void* const* d_in, const int* in_sizes, int n_in,
                              void* d_out, int out_size) {
    const int*   e           = (const int*)  d_in[0];
    const int*   q           = (const int*)  d_in[1];
    const int*   r_space     = (const int*)  d_in[2];
    const int*   e_space     = (const int*)  d_in[3];
    const int*   action_mask = (const int*)  d_in[4];
    const float* H           = (const float*)d_in[5];
    const float* entity_emb  = (const float*)d_in[6];
    const float* relation_emb= (const float*)d_in[7];
    const float* W1          = (const float*)d_in[8];
    const float* b1          = (const float*)d_in[9];
    const float* W2          = (const float*)d_in[10];
    const float* b2          = (const float*)d_in[11];

    float* out_dist = (float*)d_out;
    float* out_ent  = out_dist + (long)BATCH * NACT;
    int write_ent = (out_size >= BATCH * NACT + BATCH) ? 1 : 0;

    int nrel = in_sizes[7] / RD;   // 500

    float* H1 = nullptr;  cudaGetSymbolAddress((void**)&H1,  g_H1);
    float* X2 = nullptr;  cudaGetSymbolAddress((void**)&X2,  g_X2);
    float* Sr = nullptr;  cudaGetSymbolAddress((void**)&Sr,  g_Srel);

    // 1) H1 = relu(X @ W1 + b1), X built on the fly inside the A-loader
    {
        dim3 grid((AD + BN - 1) / BN, BATCH / BM);
        sgemm_bias_kernel<true><<<grid, 256>>>(
            nullptr, W1, b1, H1, BATCH, AD, K1, 1,
            e, q, H, entity_emb, relation_emb);
    }
    // 2) X2 = H1 @ W2 + b2
    {
        dim3 grid((AD + BN - 1) / BN, BATCH / BM);
        sgemm_bias_kernel<false><<<grid, 256>>>(
            H1, W2, b2, X2, BATCH, AD, AD, 0,
            nullptr, nullptr, nullptr, nullptr, nullptr);
    }
    // 3) S_rel = X2[:, :200] @ rel_emb^T   [2048, 512(padded)]
    {
        dim3 grid(NRELPAD / BN, BATCH / BM);
        srel_gemm_kernel<<<grid, 256>>>(X2, relation_emb, Sr, nrel);
    }
    // 4) entity gather-dot + rel lookup + softmax + entropy
    {
        scores_kernel<<<BATCH, 256>>>(r_space, e_space, action_mask,
                                      entity_emb, out_dist, out_ent, write_ent);
    }
}